// round 10
// baseline (speedup 1.0000x reference)
#include <cuda_runtime.h>
#include <cstdint>

#define N0    256000
#define IN_CH 602
#define HID   256
#define NT1   10240
#define NT2   1024
#define E1    256000
#define E2    10240

#define K1P   608           // per-half padded K: 602 + 6
#define K2P   512

// ---------------- device scratch (no allocation allowed) ----------------
__device__ int g_cnt1[NT1];
__device__ int g_rowptr1[NT1 + 1];
__device__ int g_fill1[NT1];
__device__ int g_csr1[E1];

__device__ int g_cnt2[NT2];
__device__ int g_rowptr2[NT2 + 1];
__device__ int g_fill2[NT2];
__device__ int g_csr2[E2];

__device__ float g_Agg[(size_t)NT1 * K1P];  // [agg1 | pad0] tf32-rounded
__device__ float g_Xr [(size_t)NT1 * K1P];  // [x_root | pad0] tf32-rounded
__device__ float g_B1l[(size_t)K1P * HID];  // [W1l; 0]
__device__ float g_B1r[(size_t)K1P * HID];  // [W1r; 0]
__device__ float g_h  [(size_t)NT1 * HID];  // tf32-rounded post-relu
__device__ float g_A2 [(size_t)NT2 * K2P];  // [agg2 | h_root]
__device__ float g_B2 [(size_t)K2P * HID];  // [W2l; W2r]

__device__ __forceinline__ uint32_t f2tf(float f) {
    uint32_t r;
    asm("cvt.rna.tf32.f32 %0, %1;" : "=r"(r) : "f"(f));
    return r;
}
__device__ __forceinline__ float tfr(float f) { return __uint_as_float(f2tf(f)); }

// ---------------- hist ----------------
__global__ void hist_kernel(const int* __restrict__ d1, const int* __restrict__ d2) {
    int i = blockIdx.x * blockDim.x + threadIdx.x;
    if (i < E1) atomicAdd(&g_cnt1[d1[i]], 1);
    if (i < E2) atomicAdd(&g_cnt2[d2[i]], 1);
}

// ---------------- pack (side stream; independent of CSR) ----------------
#define PK_S1 (NT1 * IN_CH)     // x_root -> Xr
#define PK_S2 (NT1 * 6)         // Xr pad
#define PK_S3 (NT1 * 6)         // Agg pad
#define PK_S4 (K1P * HID)       // B1l
#define PK_S5 (K1P * HID)       // B1r
#define PK_S6 (K2P * HID)       // B2
#define PK_TOTAL (PK_S1 + PK_S2 + PK_S3 + PK_S4 + PK_S5 + PK_S6)

__global__ void pack_kernel(const float* __restrict__ x,
                            const float* __restrict__ W1l, const float* __restrict__ W1r,
                            const float* __restrict__ W2l, const float* __restrict__ W2r) {
    int i = blockIdx.x * blockDim.x + threadIdx.x;
    if (i < PK_S1) {
        int r = i / IN_CH, c = i - r * IN_CH;
        g_Xr[(size_t)r * K1P + c] = tfr(x[(size_t)r * IN_CH + c]);
        return;
    }
    i -= PK_S1;
    if (i < PK_S2) { int r = i / 6, c = i - r * 6; g_Xr [(size_t)r * K1P + IN_CH + c] = 0.f; return; }
    i -= PK_S2;
    if (i < PK_S3) { int r = i / 6, c = i - r * 6; g_Agg[(size_t)r * K1P + IN_CH + c] = 0.f; return; }
    i -= PK_S3;
    if (i < PK_S4) {
        int k = i >> 8, n = i & 255;
        g_B1l[i] = tfr(k < IN_CH ? W1l[k * HID + n] : 0.f);
        return;
    }
    i -= PK_S4;
    if (i < PK_S5) {
        int k = i >> 8, n = i & 255;
        g_B1r[i] = tfr(k < IN_CH ? W1r[k * HID + n] : 0.f);
        return;
    }
    i -= PK_S5;
    if (i >= 0 && i < PK_S6) {
        int k = i >> 8, n = i & 255;
        float v = (k < HID) ? W2l[k * HID + n] : W2r[(k - HID) * HID + n];
        g_B2[i] = tfr(v);
    }
}

// ---------------- scan: warp-shuffle hierarchical ----------------
__global__ void scan_kernel() {
    __shared__ int wsum[32];
    int t = threadIdx.x;            // 1024 threads
    int lane = t & 31, w = t >> 5;
    if (blockIdx.x == 0) {
        const int chunk = NT1 / 1024;  // 10
        int base = t * chunk;
        int local[NT1 / 1024];
        int s = 0;
#pragma unroll
        for (int i = 0; i < chunk; i++) { local[i] = g_cnt1[base + i]; s += local[i]; }
        int v = s;
#pragma unroll
        for (int off = 1; off < 32; off <<= 1) {
            int n = __shfl_up_sync(0xffffffffu, v, off);
            if (lane >= off) v += n;
        }
        if (lane == 31) wsum[w] = v;
        __syncthreads();
        if (w == 0) {
            int ws = wsum[lane];
#pragma unroll
            for (int off = 1; off < 32; off <<= 1) {
                int n = __shfl_up_sync(0xffffffffu, ws, off);
                if (lane >= off) ws += n;
            }
            wsum[lane] = ws;
        }
        __syncthreads();
        int run = v - s + (w > 0 ? wsum[w - 1] : 0);   // exclusive prefix of thread
#pragma unroll
        for (int i = 0; i < chunk; i++) {
            g_rowptr1[base + i] = run;
            g_fill1[base + i]   = run;
            run += local[i];
        }
        if (t == 1023) g_rowptr1[NT1] = run;
    } else {
        int s = g_cnt2[t];
        int v = s;
#pragma unroll
        for (int off = 1; off < 32; off <<= 1) {
            int n = __shfl_up_sync(0xffffffffu, v, off);
            if (lane >= off) v += n;
        }
        if (lane == 31) wsum[w] = v;
        __syncthreads();
        if (w == 0) {
            int ws = wsum[lane];
#pragma unroll
            for (int off = 1; off < 32; off <<= 1) {
                int n = __shfl_up_sync(0xffffffffu, ws, off);
                if (lane >= off) ws += n;
            }
            wsum[lane] = ws;
        }
        __syncthreads();
        int excl = v - s + (w > 0 ? wsum[w - 1] : 0);
        g_rowptr2[t] = excl;
        g_fill2[t]   = excl;
        if (t == 1023) g_rowptr2[NT2] = excl + s;
    }
}

// ---------------- scatter + re-zero counts ----------------
__global__ void scatter_zero_kernel(const int* __restrict__ s1, const int* __restrict__ d1,
                                    const int* __restrict__ s2, const int* __restrict__ d2) {
    int i = blockIdx.x * blockDim.x + threadIdx.x;
    if (i < E1) {
        int p = atomicAdd(&g_fill1[d1[i]], 1);
        g_csr1[p] = s1[i];
    }
    if (i < E2) {
        int p = atomicAdd(&g_fill2[d2[i]], 1);
        g_csr2[p] = s2[i];
    }
    if (i < NT1) g_cnt1[i] = 0;
    if (i < NT2) g_cnt2[i] = 0;
}

// ---------------- layer-1 aggregation -> g_Agg (tf32-rounded) ----------------------
__global__ void agg1_kernel(const float* __restrict__ x) {
    int dst = blockIdx.x;
    int t = threadIdx.x;  // 128 threads
    int beg = g_rowptr1[dst], end = g_rowptr1[dst + 1];
    float2 a0 = {0.f, 0.f}, a1 = {0.f, 0.f}, a2 = {0.f, 0.f};
    const bool has3 = (t < 45);  // 301 float2 per row
    int i = beg;
    for (; i + 4 <= end; i += 4) {
        int j0 = g_csr1[i], j1 = g_csr1[i + 1], j2 = g_csr1[i + 2], j3 = g_csr1[i + 3];
        const float2* p0 = (const float2*)(x + (size_t)j0 * IN_CH);
        const float2* p1 = (const float2*)(x + (size_t)j1 * IN_CH);
        const float2* p2 = (const float2*)(x + (size_t)j2 * IN_CH);
        const float2* p3 = (const float2*)(x + (size_t)j3 * IN_CH);
        float2 u0 = p0[t], u1 = p1[t], u2 = p2[t], u3 = p3[t];
        float2 v0 = p0[t + 128], v1 = p1[t + 128], v2 = p2[t + 128], v3 = p3[t + 128];
        float2 w0 = {0.f,0.f}, w1 = {0.f,0.f}, w2 = {0.f,0.f}, w3 = {0.f,0.f};
        if (has3) { w0 = p0[t + 256]; w1 = p1[t + 256]; w2 = p2[t + 256]; w3 = p3[t + 256]; }
        a0.x += u0.x + u1.x + u2.x + u3.x; a0.y += u0.y + u1.y + u2.y + u3.y;
        a1.x += v0.x + v1.x + v2.x + v3.x; a1.y += v0.y + v1.y + v2.y + v3.y;
        a2.x += w0.x + w1.x + w2.x + w3.x; a2.y += w0.y + w1.y + w2.y + w3.y;
    }
    for (; i < end; i++) {
        const float2* p = (const float2*)(x + (size_t)g_csr1[i] * IN_CH);
        float2 u = p[t], v = p[t + 128];
        a0.x += u.x; a0.y += u.y; a1.x += v.x; a1.y += v.y;
        if (has3) { float2 w = p[t + 256]; a2.x += w.x; a2.y += w.y; }
    }
    int deg = end - beg;
    float s = 1.f / (float)(deg > 1 ? deg : 1);
    float2* o = (float2*)(g_Agg + (size_t)dst * K1P);
    o[t]       = make_float2(tfr(a0.x * s), tfr(a0.y * s));
    o[t + 128] = make_float2(tfr(a1.x * s), tfr(a1.y * s));
    if (has3) o[t + 256] = make_float2(tfr(a2.x * s), tfr(a2.y * s));
}

// ---------------- layer-2 aggregation + h_root copy -> A2 --------------------------
__global__ void agg2_kernel() {
    int dst = blockIdx.x;
    int t = threadIdx.x;  // 128
    int beg = g_rowptr2[dst], end = g_rowptr2[dst + 1];
    float2 a = {0.f, 0.f};
    int i = beg;
    for (; i + 4 <= end; i += 4) {
        int j0 = g_csr2[i], j1 = g_csr2[i + 1], j2 = g_csr2[i + 2], j3 = g_csr2[i + 3];
        float2 u0 = ((const float2*)(g_h + (size_t)j0 * HID))[t];
        float2 u1 = ((const float2*)(g_h + (size_t)j1 * HID))[t];
        float2 u2 = ((const float2*)(g_h + (size_t)j2 * HID))[t];
        float2 u3 = ((const float2*)(g_h + (size_t)j3 * HID))[t];
        a.x += u0.x + u1.x + u2.x + u3.x;
        a.y += u0.y + u1.y + u2.y + u3.y;
    }
    for (; i < end; i++) {
        float2 u = ((const float2*)(g_h + (size_t)g_csr2[i] * HID))[t];
        a.x += u.x; a.y += u.y;
    }
    int deg = end - beg;
    float s = 1.f / (float)(deg > 1 ? deg : 1);
    float2* o = (float2*)(g_A2 + (size_t)dst * K2P);
    o[t] = make_float2(tfr(a.x * s), tfr(a.y * s));
    o[128 + t] = ((const float2*)(g_h + (size_t)dst * HID))[t];
}

// ---------------- tf32 GEMM: 128x64x32, 3-stage cp.async, 1 barrier/step -----------
#define GBM 128
#define GBN 64
#define GBK 32
#define A_STG (GBM * GBK)
#define B_STG (GBK * GBN)
#define STG_F (A_STG + B_STG)        // 24 KB per stage; x3 = 72 KB dynamic
#define GEMM_SMEM (3 * STG_F * 4)

__device__ __forceinline__ int a_idx(int m, int k) {
    return m * 32 + (((k >> 2) ^ (m & 7)) << 2) + (k & 3);
}
__device__ __forceinline__ int b_idx(int k, int n) {
    return k * 64 + ((((n >> 2) ^ ((k & 3) << 1)) & 15) << 2) + (n & 3);
}

__device__ __forceinline__ void cp16(float* s, const float* g) {
    unsigned sa = (unsigned)__cvta_generic_to_shared(s);
    asm volatile("cp.async.cg.shared.global [%0], [%1], 16;\n" :: "r"(sa), "l"(g));
}

__global__ void __launch_bounds__(256) gemm_tf32(
    const float* __restrict__ A, int ldk,
    const float* __restrict__ B,
    const float* __restrict__ bias, float* __restrict__ C,
    int S, int initC, int relu_round)
{
    extern __shared__ float smem[];
    const int tid = threadIdx.x;
    const int lane = tid & 31, warp = tid >> 5;
    const int wm = (warp & 3) * 32;
    const int wn = (warp >> 2) * 32;
    const int bM = blockIdx.x * GBM, bN = blockIdx.y * GBN;
    const int g = lane >> 2, tg = lane & 3;

    float acc[2][4][4];
    if (initC) {
#pragma unroll
        for (int mt = 0; mt < 2; mt++)
#pragma unroll
            for (int nt = 0; nt < 4; nt++) {
                int row = bM + wm + mt * 16 + g;
                int col = bN + wn + nt * 8 + tg * 2;
                float2 c0 = *reinterpret_cast<const float2*>(&C[(size_t)row * HID + col]);
                float2 c1 = *reinterpret_cast<const float2*>(&C[(size_t)(row + 8) * HID + col]);
                acc[mt][nt][0] = c0.x; acc[mt][nt][1] = c0.y;
                acc[mt][nt][2] = c1.x; acc[mt][nt][3] = c1.y;
            }
    } else {
#pragma unroll
        for (int mt = 0; mt < 2; mt++)
#pragma unroll
            for (int nt = 0; nt < 4; nt++) {
                int col = bN + wn + nt * 8 + tg * 2;
                float b0 = bias[col], b1 = bias[col + 1];
                acc[mt][nt][0] = b0; acc[mt][nt][1] = b1;
                acc[mt][nt][2] = b0; acc[mt][nt][3] = b1;
            }
    }

    const int am = tid >> 3, ac = tid & 7;
    const int bk = tid >> 4, bc = tid & 15;

    // copy stage s into buffer buf (0..2); always commits a group (possibly empty)
    auto copy_stage = [&](int s, int buf) {
        if (s < S) {
            float* As = smem + buf * STG_F;
            float* Bs = As + A_STG;
            int kb = s * GBK;
#pragma unroll
            for (int p = 0; p < 4; p++) {
                int m = am + p * 32;
                cp16(As + m * 32 + ((ac ^ (m & 7)) << 2),
                     A + (size_t)(bM + m) * ldk + kb + ac * 4);
            }
#pragma unroll
            for (int p = 0; p < 2; p++) {
                int k = bk + p * 16;
                cp16(Bs + k * 64 + (((bc ^ ((k & 3) << 1)) & 15) << 2),
                     B + (size_t)(kb + k) * HID + bN + bc * 4);
            }
        }
        asm volatile("cp.async.commit_group;\n" ::: "memory");
    };

    copy_stage(0, 0);
    copy_stage(1, 1);
    int bufC = 0;
    for (int s = 0; s < S; s++) {
        // groups retire FIFO; with uniform commits, waiting for <=1 pending
        // guarantees stage s is resident.
        asm volatile("cp.async.wait_group 1;\n" ::: "memory");
        __syncthreads();   // all warps done with step s-1 => buffer (bufC+2)%3 free
        int bufN = bufC + 2; if (bufN >= 3) bufN -= 3;
        copy_stage(s + 2, bufN);

        const float* As = smem + bufC * STG_F;
        const float* Bs = As + A_STG;
#pragma unroll
        for (int ks = 0; ks < 4; ks++) {
            int k0 = ks * 8;
            uint32_t af[2][4], bf[4][2];
#pragma unroll
            for (int mt = 0; mt < 2; mt++) {
                int m0 = wm + mt * 16 + g;
                af[mt][0] = __float_as_uint(As[a_idx(m0,     k0 + tg)]);
                af[mt][1] = __float_as_uint(As[a_idx(m0 + 8, k0 + tg)]);
                af[mt][2] = __float_as_uint(As[a_idx(m0,     k0 + tg + 4)]);
                af[mt][3] = __float_as_uint(As[a_idx(m0 + 8, k0 + tg + 4)]);
            }
#pragma unroll
            for (int nt = 0; nt < 4; nt++) {
                int n0 = wn + nt * 8 + g;
                bf[nt][0] = __float_as_uint(Bs[b_idx(k0 + tg,     n0)]);
                bf[nt][1] = __float_as_uint(Bs[b_idx(k0 + tg + 4, n0)]);
            }
#pragma unroll
            for (int mt = 0; mt < 2; mt++)
#pragma unroll
                for (int nt = 0; nt < 4; nt++) {
                    asm volatile(
                        "mma.sync.aligned.m16n8k8.row.col.f32.tf32.tf32.f32 "
                        "{%0,%1,%2,%3}, {%4,%5,%6,%7}, {%8,%9}, {%0,%1,%2,%3};\n"
                        : "+f"(acc[mt][nt][0]), "+f"(acc[mt][nt][1]),
                          "+f"(acc[mt][nt][2]), "+f"(acc[mt][nt][3])
                        : "r"(af[mt][0]), "r"(af[mt][1]), "r"(af[mt][2]), "r"(af[mt][3]),
                          "r"(bf[nt][0]), "r"(bf[nt][1]));
                }
        }
        bufC = bufC + 1; if (bufC >= 3) bufC -= 3;
    }

#pragma unroll
    for (int mt = 0; mt < 2; mt++)
#pragma unroll
        for (int nt = 0; nt < 4; nt++) {
            int row = bM + wm + mt * 16 + g;
            int col = bN + wn + nt * 8 + tg * 2;
            float v0 = acc[mt][nt][0], v1 = acc[mt][nt][1];
            float v2 = acc[mt][nt][2], v3 = acc[mt][nt][3];
            if (relu_round) {
                v0 = tfr(fmaxf(v0, 0.f)); v1 = tfr(fmaxf(v1, 0.f));
                v2 = tfr(fmaxf(v2, 0.f)); v3 = tfr(fmaxf(v3, 0.f));
            }
            *reinterpret_cast<float2*>(&C[(size_t)row * HID + col])       = make_float2(v0, v1);
            *reinterpret_cast<float2*>(&C[(size_t)(row + 8) * HID + col]) = make_float2(v2, v3);
        }
}

// ---------------- launch (r7 schedule: Xr-gemm overlaps CSR+agg1) -------------------
extern "C" void kernel_launch(void* const* d_in, const int* in_sizes, int n_in,
                              void* d_out, int out_size) {
    const float* x   = (const float*)d_in[0];
    const int* src1  = (const int*)d_in[1];
    const int* dst1  = (const int*)d_in[2];
    const int* src2  = (const int*)d_in[3];
    const int* dst2  = (const int*)d_in[4];
    const float* W1l = (const float*)d_in[5];
    const float* b1  = (const float*)d_in[6];
    const float* W1r = (const float*)d_in[7];
    const float* W2l = (const float*)d_in[8];
    const float* b2  = (const float*)d_in[9];
    const float* W2r = (const float*)d_in[10];
    float* out = (float*)d_out;

    float *pAgg, *pXr, *pB1l, *pB1r, *ph, *pA2, *pB2;
    cudaGetSymbolAddress((void**)&pAgg, g_Agg);
    cudaGetSymbolAddress((void**)&pXr,  g_Xr);
    cudaGetSymbolAddress((void**)&pB1l, g_B1l);
    cudaGetSymbolAddress((void**)&pB1r, g_B1r);
    cudaGetSymbolAddress((void**)&ph,   g_h);
    cudaGetSymbolAddress((void**)&pA2,  g_A2);
    cudaGetSymbolAddress((void**)&pB2,  g_B2);

    static cudaStream_t s2 = nullptr;
    static cudaEvent_t evFork = nullptr, evXg = nullptr;
    if (s2 == nullptr) {
        cudaStreamCreateWithFlags(&s2, cudaStreamNonBlocking);
        cudaEventCreateWithFlags(&evFork, cudaEventDisableTiming);
        cudaEventCreateWithFlags(&evXg,   cudaEventDisableTiming);
        cudaFuncSetAttribute(gemm_tf32, cudaFuncAttributeMaxDynamicSharedMemorySize,
                             GEMM_SMEM);
    }

    // fork point
    cudaEventRecord(evFork, 0);
    cudaStreamWaitEvent(s2, evFork, 0);

    // side stream: pack -> Xr gemm (h = Xr@W1r + b1, all rows)
    pack_kernel<<<(PK_TOTAL + 255) / 256, 256, 0, s2>>>(x, W1l, W1r, W2l, W2r);
    gemm_tf32<<<dim3(NT1 / GBM, HID / GBN), 256, GEMM_SMEM, s2>>>(
        pXr, K1P, pB1r, b1, ph, K1P / GBK, 0, 0);
    cudaEventRecord(evXg, s2);

    // main: CSR build (counts zero at entry; re-zeroed by scatter_zero)
    hist_kernel<<<(E1 + 255) / 256, 256>>>(dst1, dst2);
    scan_kernel<<<2, 1024>>>();
    scatter_zero_kernel<<<(E1 + 255) / 256, 256>>>(src1, dst1, src2, dst2);

    // main: full agg1
    agg1_kernel<<<NT1, 128>>>(x);

    // join: h = relu(Agg @ W1l + h), tf32-rounded
    cudaStreamWaitEvent(0, evXg, 0);
    gemm_tf32<<<dim3(NT1 / GBM, HID / GBN), 256, GEMM_SMEM>>>(
        pAgg, K1P, pB1l, nullptr, ph, K1P / GBK, 1, 1);
    agg2_kernel<<<NT2, 128>>>();
    gemm_tf32<<<dim3(NT2 / GBM, HID / GBN), 256, GEMM_SMEM>>>(
        pA2, K2P, pB2, b2, out, K2P / GBK, 0, 0);
}

// round 13
// speedup vs baseline: 1.0889x; 1.0889x over previous
#include <cuda_runtime.h>
#include <cstdint>

#define N0    256000
#define IN_CH 602
#define HID   256
#define NT1   10240
#define NT2   1024
#define E1    256000
#define E2    10240

#define K1P   608
#define K2P   512

__device__ int g_cnt1[NT1];
__device__ int g_rowptr1[NT1 + 1];
__device__ int g_fill1[NT1];
__device__ int g_csr1[E1];

__device__ int g_cnt2[NT2];
__device__ int g_rowptr2[NT2 + 1];
__device__ int g_fill2[NT2];
__device__ int g_csr2[E2];

__device__ unsigned g_tick;

__device__ float g_Agg[(size_t)NT1 * K1P];
__device__ float g_Xr [(size_t)NT1 * K1P];
__device__ float g_B1l[(size_t)K1P * HID];
__device__ float g_B1r[(size_t)K1P * HID];
__device__ float g_h  [(size_t)NT1 * HID];
__device__ float g_A2 [(size_t)NT2 * K2P];
__device__ float g_B2 [(size_t)K2P * HID];

__device__ __forceinline__ uint32_t f2tf(float f) {
    uint32_t r;
    asm("cvt.rna.tf32.f32 %0, %1;" : "=r"(r) : "f"(f));
    return r;
}
__device__ __forceinline__ float tfr(float f) { return __uint_as_float(f2tf(f)); }

// ---------------- fused hist + scan (last-block pattern) ----------------
__global__ void hist_scan_kernel(const int* __restrict__ d1, const int* __restrict__ d2) {
    int i = blockIdx.x * blockDim.x + threadIdx.x;
    if (i < E1) atomicAdd(&g_cnt1[d1[i]], 1);
    if (i < E2) atomicAdd(&g_cnt2[d2[i]], 1);
    __threadfence();
    __shared__ bool isLast;
    __syncthreads();
    if (threadIdx.x == 0) {
        unsigned t = atomicAdd(&g_tick, 1u);
        isLast = (t == gridDim.x - 1);
    }
    __syncthreads();
    if (!isLast) return;

    if (threadIdx.x == 0) g_tick = 0;
    __threadfence();
    const int tid = threadIdx.x;
    const int lane = tid & 31, w = tid >> 5;
    __shared__ int wsum[8];

    {   // scan cnt1: 256 threads x 40
        int base = tid * 40;
        int s = 0;
#pragma unroll
        for (int j = 0; j < 40; j++) s += g_cnt1[base + j];
        int v = s;
#pragma unroll
        for (int off = 1; off < 32; off <<= 1) {
            int n = __shfl_up_sync(0xffffffffu, v, off);
            if (lane >= off) v += n;
        }
        if (lane == 31) wsum[w] = v;
        __syncthreads();
        if (w == 0) {
            int ws = (lane < 8) ? wsum[lane] : 0;
#pragma unroll
            for (int off = 1; off < 32; off <<= 1) {
                int n = __shfl_up_sync(0xffffffffu, ws, off);
                if (lane >= off) ws += n;
            }
            if (lane < 8) wsum[lane] = ws;
        }
        __syncthreads();
        int run = v - s + (w > 0 ? wsum[w - 1] : 0);
#pragma unroll
        for (int j = 0; j < 40; j++) {
            int c = g_cnt1[base + j];
            g_rowptr1[base + j] = run;
            g_fill1[base + j]   = run;
            run += c;
        }
        if (tid == 255) g_rowptr1[NT1] = run;
    }
    __syncthreads();
    {   // scan cnt2: 256 threads x 4
        int base = tid * 4;
        int s = 0;
#pragma unroll
        for (int j = 0; j < 4; j++) s += g_cnt2[base + j];
        int v = s;
#pragma unroll
        for (int off = 1; off < 32; off <<= 1) {
            int n = __shfl_up_sync(0xffffffffu, v, off);
            if (lane >= off) v += n;
        }
        if (lane == 31) wsum[w] = v;
        __syncthreads();
        if (w == 0) {
            int ws = (lane < 8) ? wsum[lane] : 0;
#pragma unroll
            for (int off = 1; off < 32; off <<= 1) {
                int n = __shfl_up_sync(0xffffffffu, ws, off);
                if (lane >= off) ws += n;
            }
            if (lane < 8) wsum[lane] = ws;
        }
        __syncthreads();
        int run = v - s + (w > 0 ? wsum[w - 1] : 0);
#pragma unroll
        for (int j = 0; j < 4; j++) {
            int c = g_cnt2[base + j];
            g_rowptr2[base + j] = run;
            g_fill2[base + j]   = run;
            run += c;
        }
        if (tid == 255) g_rowptr2[NT2] = run;
    }
}

// ---------------- pack_xr: Xr (float2) + B1r ----------------
#define PXR_N  (NT1 * 304)
#define PB1R_N (K1P * HID)
#define PXR_TOTAL (PXR_N + PB1R_N)

__global__ void pack_xr_kernel(const float* __restrict__ x, const float* __restrict__ W1r) {
    int i = blockIdx.x * blockDim.x + threadIdx.x;
    if (i < PXR_N) {
        int r = i / 304, c = i - r * 304;
        float2 v = {0.f, 0.f};
        if (c < 301) {
            float2 u = ((const float2*)(x + (size_t)r * IN_CH))[c];
            v.x = tfr(u.x); v.y = tfr(u.y);
        }
        ((float2*)(g_Xr + (size_t)r * K1P))[c] = v;
        return;
    }
    i -= PXR_N;
    if (i >= 0 && i < PB1R_N) {
        int k = i >> 8, n = i & 255;
        g_B1r[i] = tfr(k < IN_CH ? W1r[k * HID + n] : 0.f);
    }
}

// ---------------- pack_w: B1l, B2, Agg pads ----------------
#define PW1 (K1P * HID)
#define PW2 (K2P * HID)
#define PW3 (NT1 * 6)
#define PW_TOTAL (PW1 + PW2 + PW3)

__global__ void pack_w_kernel(const float* __restrict__ W1l,
                              const float* __restrict__ W2l, const float* __restrict__ W2r) {
    int i = blockIdx.x * blockDim.x + threadIdx.x;
    if (i < PW1) {
        int k = i >> 8, n = i & 255;
        g_B1l[i] = tfr(k < IN_CH ? W1l[k * HID + n] : 0.f);
        return;
    }
    i -= PW1;
    if (i < PW2) {
        int k = i >> 8, n = i & 255;
        float v = (k < HID) ? W2l[k * HID + n] : W2r[(k - HID) * HID + n];
        g_B2[i] = tfr(v);
        return;
    }
    i -= PW2;
    if (i >= 0 && i < PW3) {
        int r = i / 6, c = i - r * 6;
        g_Agg[(size_t)r * K1P + IN_CH + c] = 0.f;
    }
}

// ---------------- scatter + re-zero counts ----------------
__global__ void scatter_zero_kernel(const int* __restrict__ s1, const int* __restrict__ d1,
                                    const int* __restrict__ s2, const int* __restrict__ d2) {
    int i = blockIdx.x * blockDim.x + threadIdx.x;
    if (i < E1) {
        int p = atomicAdd(&g_fill1[d1[i]], 1);
        g_csr1[p] = s1[i];
    }
    if (i < E2) {
        int p = atomicAdd(&g_fill2[d2[i]], 1);
        g_csr2[p] = s2[i];
    }
    if (i < NT1) g_cnt1[i] = 0;
    if (i < NT2) g_cnt2[i] = 0;
}

// ---------------- layer-1 aggregation ----------------
__global__ void agg1_kernel(const float* __restrict__ x) {
    int dst = blockIdx.x;
    int t = threadIdx.x;
    int beg = g_rowptr1[dst], end = g_rowptr1[dst + 1];
    float2 a0 = {0.f, 0.f}, a1 = {0.f, 0.f}, a2 = {0.f, 0.f};
    const bool has3 = (t < 45);
    int i = beg;
    for (; i + 4 <= end; i += 4) {
        int j0 = g_csr1[i], j1 = g_csr1[i + 1], j2 = g_csr1[i + 2], j3 = g_csr1[i + 3];
        const float2* p0 = (const float2*)(x + (size_t)j0 * IN_CH);
        const float2* p1 = (const float2*)(x + (size_t)j1 * IN_CH);
        const float2* p2 = (const float2*)(x + (size_t)j2 * IN_CH);
        const float2* p3 = (const float2*)(x + (size_t)j3 * IN_CH);
        float2 u0 = p0[t], u1 = p1[t], u2 = p2[t], u3 = p3[t];
        float2 v0 = p0[t + 128], v1 = p1[t + 128], v2 = p2[t + 128], v3 = p3[t + 128];
        float2 w0 = {0.f,0.f}, w1 = {0.f,0.f}, w2 = {0.f,0.f}, w3 = {0.f,0.f};
        if (has3) { w0 = p0[t + 256]; w1 = p1[t + 256]; w2 = p2[t + 256]; w3 = p3[t + 256]; }
        a0.x += u0.x + u1.x + u2.x + u3.x; a0.y += u0.y + u1.y + u2.y + u3.y;
        a1.x += v0.x + v1.x + v2.x + v3.x; a1.y += v0.y + v1.y + v2.y + v3.y;
        a2.x += w0.x + w1.x + w2.x + w3.x; a2.y += w0.y + w1.y + w2.y + w3.y;
    }
    for (; i < end; i++) {
        const float2* p = (const float2*)(x + (size_t)g_csr1[i] * IN_CH);
        float2 u = p[t], v = p[t + 128];
        a0.x += u.x; a0.y += u.y; a1.x += v.x; a1.y += v.y;
        if (has3) { float2 w = p[t + 256]; a2.x += w.x; a2.y += w.y; }
    }
    int deg = end - beg;
    float s = 1.f / (float)(deg > 1 ? deg : 1);
    float2* o = (float2*)(g_Agg + (size_t)dst * K1P);
    o[t]       = make_float2(tfr(a0.x * s), tfr(a0.y * s));
    o[t + 128] = make_float2(tfr(a1.x * s), tfr(a1.y * s));
    if (has3) o[t + 256] = make_float2(tfr(a2.x * s), tfr(a2.y * s));
}

// ---------------- layer-2 aggregation + h_root copy ----------------
__global__ void agg2_kernel() {
    int dst = blockIdx.x;
    int t = threadIdx.x;
    int beg = g_rowptr2[dst], end = g_rowptr2[dst + 1];
    float2 a = {0.f, 0.f};
    int i = beg;
    for (; i + 4 <= end; i += 4) {
        int j0 = g_csr2[i], j1 = g_csr2[i + 1], j2 = g_csr2[i + 2], j3 = g_csr2[i + 3];
        float2 u0 = ((const float2*)(g_h + (size_t)j0 * HID))[t];
        float2 u1 = ((const float2*)(g_h + (size_t)j1 * HID))[t];
        float2 u2 = ((const float2*)(g_h + (size_t)j2 * HID))[t];
        float2 u3 = ((const float2*)(g_h + (size_t)j3 * HID))[t];
        a.x += u0.x + u1.x + u2.x + u3.x;
        a.y += u0.y + u1.y + u2.y + u3.y;
    }
    for (; i < end; i++) {
        float2 u = ((const float2*)(g_h + (size_t)g_csr2[i] * HID))[t];
        a.x += u.x; a.y += u.y;
    }
    int deg = end - beg;
    float s = 1.f / (float)(deg > 1 ? deg : 1);
    float2* o = (float2*)(g_A2 + (size_t)dst * K2P);
    o[t] = make_float2(tfr(a.x * s), tfr(a.y * s));
    o[128 + t] = ((const float2*)(g_h + (size_t)dst * HID))[t];
}

// ---------------- tf32 GEMM: 128x64x32, 2-stage cp.async ----------------
#define GBM 128
#define GBN 64
#define GBK 32
#define A_STG (GBM * GBK)
#define B_STG (GBK * GBN)
#define STG_F (A_STG + B_STG)

__device__ __forceinline__ int a_idx(int m, int k) {
    return m * 32 + (((k >> 2) ^ (m & 7)) << 2) + (k & 3);
}
__device__ __forceinline__ int b_idx(int k, int n) {
    return k * 64 + ((((n >> 2) ^ ((k & 3) << 1)) & 15) << 2) + (n & 3);
}

__device__ __forceinline__ void cp16(float* s, const float* g) {
    unsigned sa = (unsigned)__cvta_generic_to_shared(s);
    asm volatile("cp.async.cg.shared.global [%0], [%1], 16;\n" :: "r"(sa), "l"(g));
}

__global__ void __launch_bounds__(256) gemm_tf32(
    const float* __restrict__ A, int ldk,
    const float* __restrict__ B,
    const float* __restrict__ bias, float* __restrict__ C,
    int S, int initC, int relu_round)
{
    __shared__ float smem[2 * STG_F];
    const int tid = threadIdx.x;
    const int lane = tid & 31, warp = tid >> 5;
    const int wm = (warp & 3) * 32;
    const int wn = (warp >> 2) * 32;
    const int bM = blockIdx.x * GBM, bN = blockIdx.y * GBN;
    const int g = lane >> 2, tg = lane & 3;

    float acc[2][4][4];
    if (initC) {
#pragma unroll
        for (int mt = 0; mt < 2; mt++)
#pragma unroll
            for (int nt = 0; nt < 4; nt++) {
                int row = bM + wm + mt * 16 + g;
                int col = bN + wn + nt * 8 + tg * 2;
                float2 c0 = *reinterpret_cast<const float2*>(&C[(size_t)row * HID + col]);
                float2 c1 = *reinterpret_cast<const float2*>(&C[(size_t)(row + 8) * HID + col]);
                acc[mt][nt][0] = c0.x; acc[mt][nt][1] = c0.y;
                acc[mt][nt][2] = c1.x; acc[mt][nt][3] = c1.y;
            }
    } else {
#pragma unroll
        for (int mt = 0; mt < 2; mt++)
#pragma unroll
            for (int nt = 0; nt < 4; nt++) {
                int col = bN + wn + nt * 8 + tg * 2;
                float b0 = bias[col], b1 = bias[col + 1];
                acc[mt][nt][0] = b0; acc[mt][nt][1] = b1;
                acc[mt][nt][2] = b0; acc[mt][nt][3] = b1;
            }
    }

    const int am = tid >> 3, ac = tid & 7;
    const int bk = tid >> 4, bc = tid & 15;

    auto copy_stage = [&](int s) {
        float* As = smem + (s & 1) * STG_F;
        float* Bs = As + A_STG;
        int kb = s * GBK;
#pragma unroll
        for (int p = 0; p < 4; p++) {
            int m = am + p * 32;
            cp16(As + m * 32 + ((ac ^ (m & 7)) << 2),
                 A + (size_t)(bM + m) * ldk + kb + ac * 4);
        }
#pragma unroll
        for (int p = 0; p < 2; p++) {
            int k = bk + p * 16;
            cp16(Bs + k * 64 + (((bc ^ ((k & 3) << 1)) & 15) << 2),
                 B + (size_t)(kb + k) * HID + bN + bc * 4);
        }
        asm volatile("cp.async.commit_group;\n" ::: "memory");
    };

    copy_stage(0);
    for (int s = 0; s < S; s++) {
        asm volatile("cp.async.wait_group 0;\n" ::: "memory");
        __syncthreads();
        if (s + 1 < S) copy_stage(s + 1);
        const float* As = smem + (s & 1) * STG_F;
        const float* Bs = As + A_STG;
#pragma unroll
        for (int ks = 0; ks < 4; ks++) {
            int k0 = ks * 8;
            uint32_t af[2][4], bf[4][2];
#pragma unroll
            for (int mt = 0; mt < 2; mt++) {
                int m0 = wm + mt * 16 + g;
                af[mt][0] = __float_as_uint(As[a_idx(m0,     k0 + tg)]);
                af[mt][1] = __float_as_uint(As[a_idx(m0 + 8, k0 + tg)]);
                af[mt][2] = __float_as_uint(As[a_idx(m0,     k0 + tg + 4)]);
                af[mt][3] = __float_as_uint(As[a_idx(m0 + 8, k0 + tg + 4)]);
            }
#pragma unroll
            for (int nt = 0; nt < 4; nt++) {
                int n0 = wn + nt * 8 + g;
                bf[nt][0] = __float_as_uint(Bs[b_idx(k0 + tg,     n0)]);
                bf[nt][1] = __float_as_uint(Bs[b_idx(k0 + tg + 4, n0)]);
            }
#pragma unroll
            for (int mt = 0; mt < 2; mt++)
#pragma unroll
                for (int nt = 0; nt < 4; nt++) {
                    asm volatile(
                        "mma.sync.aligned.m16n8k8.row.col.f32.tf32.tf32.f32 "
                        "{%0,%1,%2,%3}, {%4,%5,%6,%7}, {%8,%9}, {%0,%1,%2,%3};\n"
                        : "+f"(acc[mt][nt][0]), "+f"(acc[mt][nt][1]),
                          "+f"(acc[mt][nt][2]), "+f"(acc[mt][nt][3])
                        : "r"(af[mt][0]), "r"(af[mt][1]), "r"(af[mt][2]), "r"(af[mt][3]),
                          "r"(bf[nt][0]), "r"(bf[nt][1]));
                }
        }
        __syncthreads();
    }

#pragma unroll
    for (int mt = 0; mt < 2; mt++)
#pragma unroll
        for (int nt = 0; nt < 4; nt++) {
            int row = bM + wm + mt * 16 + g;
            int col = bN + wn + nt * 8 + tg * 2;
            float v0 = acc[mt][nt][0], v1 = acc[mt][nt][1];
            float v2 = acc[mt][nt][2], v3 = acc[mt][nt][3];
            if (relu_round) {
                v0 = tfr(fmaxf(v0, 0.f)); v1 = tfr(fmaxf(v1, 0.f));
                v2 = tfr(fmaxf(v2, 0.f)); v3 = tfr(fmaxf(v3, 0.f));
            }
            *reinterpret_cast<float2*>(&C[(size_t)row * HID + col])       = make_float2(v0, v1);
            *reinterpret_cast<float2*>(&C[(size_t)(row + 8) * HID + col]) = make_float2(v2, v3);
        }
}

// ---------------- launch ----------------
extern "C" void kernel_launch(void* const* d_in, const int* in_sizes, int n_in,
                              void* d_out, int out_size) {
    const float* x   = (const float*)d_in[0];
    const int* src1  = (const int*)d_in[1];
    const int* dst1  = (const int*)d_in[2];
    const int* src2  = (const int*)d_in[3];
    const int* dst2  = (const int*)d_in[4];
    const float* W1l = (const float*)d_in[5];
    const float* b1  = (const float*)d_in[6];
    const float* W1r = (const float*)d_in[7];
    const float* W2l = (const float*)d_in[8];
    const float* b2  = (const float*)d_in[9];
    const float* W2r = (const float*)d_in[10];
    float* out = (float*)d_out;

    float *pAgg, *pXr, *pB1l, *pB1r, *ph, *pA2, *pB2;
    cudaGetSymbolAddress((void**)&pAgg, g_Agg);
    cudaGetSymbolAddress((void**)&pXr,  g_Xr);
    cudaGetSymbolAddress((void**)&pB1l, g_B1l);
    cudaGetSymbolAddress((void**)&pB1r, g_B1r);
    cudaGetSymbolAddress((void**)&ph,   g_h);
    cudaGetSymbolAddress((void**)&pA2,  g_A2);
    cudaGetSymbolAddress((void**)&pB2,  g_B2);

    static cudaStream_t s2 = nullptr;
    static cudaEvent_t evFork = nullptr, evXg = nullptr;
    if (s2 == nullptr) {
        cudaStreamCreateWithFlags(&s2, cudaStreamNonBlocking);
        cudaEventCreateWithFlags(&evFork, cudaEventDisableTiming);
        cudaEventCreateWithFlags(&evXg,   cudaEventDisableTiming);
    }

    cudaEventRecord(evFork, 0);
    cudaStreamWaitEvent(s2, evFork, 0);

    // side: pack_xr -> Xr gemm -> pack_w
    pack_xr_kernel<<<(PXR_TOTAL + 255) / 256, 256, 0, s2>>>(x, W1r);
    gemm_tf32<<<dim3(NT1 / GBM, HID / GBN), 256, 0, s2>>>(pXr, K1P, pB1r, b1, ph,
                                                          K1P / GBK, 0, 0);
    pack_w_kernel<<<(PW_TOTAL + 255) / 256, 256, 0, s2>>>(W1l, W2l, W2r);
    cudaEventRecord(evXg, s2);

    // main: fused hist+scan, then scatter (also re-zeros counts)
    hist_scan_kernel<<<(E1 + 255) / 256, 256>>>(dst1, dst2);
    scatter_zero_kernel<<<(E1 + 255) / 256, 256>>>(src1, dst1, src2, dst2);

    // main: agg1
    agg1_kernel<<<NT1, 128>>>(x);

    // join: h = relu(Agg @ W1l + h)
    cudaStreamWaitEvent(0, evXg, 0);
    gemm_tf32<<<dim3(NT1 / GBM, HID / GBN), 256>>>(pAgg, K1P, pB1l, nullptr, ph,
                                                   K1P / GBK, 1, 1);
    agg2_kernel<<<NT2, 128>>>();
    gemm_tf32<<<dim3(NT2 / GBM, HID / GBN), 256>>>(pA2, K2P, pB2, b2, out,
                                                   K2P / GBK, 0, 0);
}